// round 9
// baseline (speedup 1.0000x reference)
#include <cuda_runtime.h>

// B3-spline undecimated wavelet transform (a trous), 3 levels, fully fused.
// x: (8, 1024, 1024) f32 -> out: (8, 4, 1024, 1024) f32 = [w1, w2, w3, c3]
//
// R9: per level, horizontal conv (W) first into a 52-row ring buffer Q, then
// vertical conv (H) Q->P in place + w/c3 emission, processed in two row-halves
// (4 phases/level). Ring shrinks smem 70.7->54KB -> 4 CTAs x 448 thr = 56
// warps/SM. Level 3 emits w3 AND c3 directly (no epilogue, no P writeback).

#define IMG   1024
#define TS    64
#define HL    14
#define S     (TS + 2*HL)   // 92
#define SP    96            // row stride (16B-aligned rows)
#define NTHR  448
#define SHIFT 2             // phys col = logical col + SHIFT
#define QROWS 52            // Q ring height

#define SMEM_FLOATS (S * SP + QROWS * SP)
#define SMEM_BYTES  (SMEM_FLOATS * sizeof(float))   // 55296 B

__device__ __forceinline__ int reflect_idx(int g) {
    if (g < 0) g = -g;
    if (g >= IMG) g = 2 * IMG - 2 - g;
    return g;
}

__device__ __forceinline__ float4 f4_add(float4 a, float4 b) {
    return make_float4(a.x + b.x, a.y + b.y, a.z + b.z, a.w + b.w);
}

// ---- W pass: horizontal conv. P rows [r0, r1), cols [a, S-a) -> Q ring.
//      Ring slot = (y - h) mod QROWS. 4-col float4 groups (conflict-free).
template<int d, int a, int h, int r0, int r1>
__device__ __forceinline__ void wpass(const float* __restrict__ P,
                                      float* __restrict__ Q) {
    const float w0 = 0.0625f, w1 = 0.25f, w2 = 0.375f;
    constexpr int n2    = S - 2 * a;
    constexpr int xg    = n2 / 4;
    constexpr int items = (r1 - r0) * xg;
    for (int idx = threadIdx.x; idx < items; idx += NTHR) {
        int g  = idx % xg;
        int y  = r0 + idx / xg;
        int x0 = a + 4 * g;                 // logical col of group
        int op = y * SP + x0 + SHIFT;       // phys, 16B-aligned
        float c0, c1, c2, c3;
        if constexpr (d == 4) {
            // taps land exactly on float4 lanes
            float4 A = *reinterpret_cast<const float4*>(&P[op - 8]);
            float4 B = *reinterpret_cast<const float4*>(&P[op - 4]);
            float4 C = *reinterpret_cast<const float4*>(&P[op]);
            float4 D = *reinterpret_cast<const float4*>(&P[op + 4]);
            float4 E = *reinterpret_cast<const float4*>(&P[op + 8]);
            float4 AE = f4_add(A, E), BD = f4_add(B, D);
            c0 = w0 * AE.x + w1 * BD.x + w2 * C.x;
            c1 = w0 * AE.y + w1 * BD.y + w2 * C.y;
            c2 = w0 * AE.z + w1 * BD.z + w2 * C.z;
            c3 = w0 * AE.w + w1 * BD.w + w2 * C.w;
        } else {
            constexpr int off = ((a - 2 * d) + SHIFT) & 3;   // 2 (d=1), 0 (d=2)
            constexpr int nw  = (4 * d + 4 + off + 3) & ~3;  // 12 / 12
            int ow = op - 2 * d - off;                        // 16B-aligned
            float v[nw];
#pragma unroll
            for (int k = 0; k < nw / 4; k++) {
                float4 t4 = *reinterpret_cast<const float4*>(&P[ow + 4 * k]);
                v[4 * k] = t4.x; v[4 * k + 1] = t4.y;
                v[4 * k + 2] = t4.z; v[4 * k + 3] = t4.w;
            }
            c0 = w2 * v[off + 2 * d]     + w1 * (v[off + d]     + v[off + 3 * d])
               + w0 * (v[off]            + v[off + 4 * d]);
            c1 = w2 * v[off + 2 * d + 1] + w1 * (v[off + d + 1] + v[off + 3 * d + 1])
               + w0 * (v[off + 1]        + v[off + 4 * d + 1]);
            c2 = w2 * v[off + 2 * d + 2] + w1 * (v[off + d + 2] + v[off + 3 * d + 2])
               + w0 * (v[off + 2]        + v[off + 4 * d + 2]);
            c3 = w2 * v[off + 2 * d + 3] + w1 * (v[off + d + 3] + v[off + 3 * d + 3])
               + w0 * (v[off + 3]        + v[off + 4 * d + 3]);
        }
        int ys = y - h; if (ys >= QROWS) ys -= QROWS;
        *reinterpret_cast<float4*>(&Q[ys * SP + x0 + SHIFT]) =
            make_float4(c0, c1, c2, c3);
    }
}

// ---- H pass: vertical conv. Q ring -> P rows [y0s, y0e) in place (unless
//      LAST), emit w = prev - c on center (and c3 if LAST). 8-row strips,
//      scalar conflict-free LDS/STS (adjacent lanes -> adjacent columns).
template<int d, int a, int h, int y0s, int y0e, bool LAST>
__device__ __forceinline__ void hpass(float* __restrict__ P,
                                      const float* __restrict__ Q,
                                      float* __restrict__ wch,
                                      float* __restrict__ cch,
                                      int ty0, int tx0) {
    const float w0 = 0.0625f, w1 = 0.25f, w2 = 0.375f;
    constexpr int nc     = S - 2 * a;          // 88 / 80 / 64
    constexpr int strips = (y0e - y0s) / 8;
    constexpr int nw     = 8 + 4 * d;          // 12 / 16 / 24
    for (int idx = threadIdx.x; idx < strips * nc; idx += NTHR) {
        int x  = idx % nc;
        int t  = idx / nc;
        int y0 = y0s + 8 * t;
        int oc = a + x + SHIFT;                // phys col
        int yb = y0 - 2 * d - h;               // ring base (may wrap once)
        float v[nw];
#pragma unroll
        for (int i = 0; i < nw; i++) {
            int ys = yb + i; if (ys >= QROWS) ys -= QROWS;
            v[i] = Q[ys * SP + oc];
        }
        bool cx = LAST || (x + a >= HL && x + a < S - HL);
        int gx = tx0 + (x + a) - HL;
#pragma unroll
        for (int i = 0; i < 8; i++) {
            float c = w2 * v[2 * d + i]
                    + w1 * (v[d + i] + v[3 * d + i])
                    + w0 * (v[i] + v[4 * d + i]);
            int y = y0 + i;
            int o = y * SP + oc;
            float prev = P[o];
            if constexpr (!LAST) P[o] = c;
            bool cy = LAST || (y >= HL && y < S - HL);
            if (cx && cy) {
                int gy = ty0 + y - HL;
                wch[gy * IMG + gx] = prev - c;
                if constexpr (LAST) cch[gy * IMG + gx] = c;
            }
        }
    }
}

// ---- one level: 4 banded phases ----
template<int d, int h, int a, int mid, bool LAST>
__device__ __forceinline__ void do_level(float* __restrict__ P,
                                         float* __restrict__ Q,
                                         float* __restrict__ wch,
                                         float* __restrict__ cch,
                                         int ty0, int tx0) {
    wpass<d, a, h, h, mid + 2 * d>(P, Q);            // Q rows [h, mid+2d)
    __syncthreads();
    hpass<d, a, h, a, mid, LAST>(P, Q, wch, cch, ty0, tx0);
    __syncthreads();
    wpass<d, a, h, mid + 2 * d, S - h>(P, Q);        // new Q rows only
    __syncthreads();
    hpass<d, a, h, mid, S - a, LAST>(P, Q, wch, cch, ty0, tx0);
}

__global__ void __launch_bounds__(NTHR, 4) uwt_kernel(const float* __restrict__ x,
                                                      float* __restrict__ out) {
    extern __shared__ float smem[];
    float* P = smem;                 // 92 x 96
    float* Q = smem + S * SP;        // 52 x 96 ring

    const int b   = blockIdx.z;
    const int ty0 = blockIdx.y * TS;
    const int tx0 = blockIdx.x * TS;
    const float* xb = x + (size_t)b * IMG * IMG;

    // ---- load c0 with halo ----
    const bool interior = (tx0 >= 64 && tx0 <= IMG - TS - 16) &&
                          (ty0 >= 64 && ty0 <= IMG - TS - 16);
    if (interior) {
        // full 96-wide rows (logical cols [-2, 94)), 16B-aligned LDG/STS.128
        const float* src = xb + (size_t)(ty0 - HL) * IMG + (tx0 - 16);
        for (int idx = threadIdx.x; idx < S * (SP / 4); idx += NTHR) {
            int ly = idx / (SP / 4);
            int k  = idx - ly * (SP / 4);
            float4 v4 = *reinterpret_cast<const float4*>(src + (size_t)ly * IMG + 4 * k);
            *reinterpret_cast<float4*>(&P[ly * SP + 4 * k]) = v4;
        }
    } else {
        for (int idx = threadIdx.x; idx < S * S; idx += NTHR) {
            int ly = idx / S;
            int lx = idx - ly * S;
            int gy = reflect_idx(ty0 + ly - HL);
            int gx = reflect_idx(tx0 + lx - HL);
            P[ly * SP + lx + SHIFT] = xb[gy * IMG + gx];
        }
    }
    __syncthreads();

    float* ob = out + (size_t)b * 4 * IMG * IMG;
    // mid chosen so both halves' strip counts divide by 8:
    // L1: [2,42)/[42,90); L2: [6,46)/[46,86); L3: [14,46)/[46,78)
    do_level<1, 0, 2, 42, false>(P, Q, ob + 0 * IMG * IMG, nullptr, ty0, tx0);
    __syncthreads();
    do_level<2, 2, 6, 46, false>(P, Q, ob + 1 * IMG * IMG, nullptr, ty0, tx0);
    __syncthreads();
    do_level<4, 6, 14, 46, true>(P, Q, ob + 2 * IMG * IMG, ob + 3 * IMG * IMG,
                                 ty0, tx0);
}

extern "C" void kernel_launch(void* const* d_in, const int* in_sizes, int n_in,
                              void* d_out, int out_size) {
    const float* x = (const float*)d_in[0];
    float* out     = (float*)d_out;

    cudaFuncSetAttribute(uwt_kernel, cudaFuncAttributeMaxDynamicSharedMemorySize,
                         (int)SMEM_BYTES);

    dim3 grid(IMG / TS, IMG / TS, 8);
    uwt_kernel<<<grid, NTHR, SMEM_BYTES>>>(x, out);
}

// round 11
// speedup vs baseline: 1.0391x; 1.0391x over previous
#include <cuda_runtime.h>

// B3-spline undecimated wavelet transform (a trous), 3 levels, fully fused.
// x: (8, 1024, 1024) f32 -> out: (8, 4, 1024, 1024) f32 = [w1, w2, w3, c3]
//
// R10: banded levels. H (vertical, into Q band) then W (horizontal, Q->P).
// W row y consumes only Q row y, so Q = one 48-row band. W1 defers its last
// 2d rows so H2's P window is untouched; W2 finishes them with a compile-time
// slot-threshold select. 52.5KB smem -> 4 CTAs x 448 thr = 56 warps/SM.
// Level 3 emits w3 + c3 directly (no P writeback, no epilogue).

#define IMG   1024
#define TS    64
#define HL    14
#define S     (TS + 2*HL)   // 92
#define SP    96            // row stride (16B-aligned rows)
#define NTHR  448
#define SHIFT 2             // phys col = logical col + SHIFT
#define QCAP  48            // Q band rows

#define SMEM_FLOATS (S * SP + QCAP * SP)
#define SMEM_BYTES  (SMEM_FLOATS * sizeof(float))   // 53760 B

__device__ __forceinline__ int reflect_idx(int g) {
    if (g < 0) g = -g;
    if (g >= IMG) g = 2 * IMG - 2 - g;
    return g;
}

__device__ __forceinline__ float4 f4_add(float4 a, float4 b) {
    return make_float4(a.x + b.x, a.y + b.y, a.z + b.z, a.w + b.w);
}

// ---- H pass (vertical conv): P rows window -> Q band. 8-row strips,
//      1 col/thread, adjacent lanes -> adjacent cols (conflict-free).
//      Q slot row = y - qoff (compile-time qoff).
template<int d, int h, int a, int y0s, int y0e, int qoff>
__device__ __forceinline__ void hpass(const float* __restrict__ P,
                                      float* __restrict__ Q) {
    const float w0 = 0.0625f, w1 = 0.25f, w2 = 0.375f;
    constexpr int strips = (y0e - y0s) / 8;
    constexpr int cols   = S - 2 * h;          // 92 / 88 / 80
    constexpr int nw     = 8 + 4 * d;          // 12 / 16 / 24
    for (int idx = threadIdx.x; idx < strips * cols; idx += NTHR) {
        int x  = idx % cols;
        int t  = idx / cols;
        int y0 = y0s + 8 * t;
        int oc = h + x + SHIFT;
        int ob = (y0 - 2 * d) * SP + oc;
        float v[nw];
#pragma unroll
        for (int i = 0; i < nw; i++) v[i] = P[ob + i * SP];
#pragma unroll
        for (int i = 0; i < 8; i++) {
            Q[(y0 + i - qoff) * SP + oc] = w2 * v[2 * d + i]
                                         + w1 * (v[d + i] + v[3 * d + i])
                                         + w0 * (v[i] + v[4 * d + i]);
        }
    }
}

// ---- W pass (horizontal conv): Q band -> P in place (unless LAST), emit
//      w = prev - c on center (and c3 if LAST). 4-col float4 groups.
//      Q slot row = y - (y < thr ? qoffA : qoffB), all compile-time consts.
template<int d, int h, int a, int r0, int r1, int thr, int qoffA, int qoffB,
         bool LAST>
__device__ __forceinline__ void wpass(float* __restrict__ P,
                                      const float* __restrict__ Q,
                                      float* __restrict__ wch,
                                      float* __restrict__ cch,
                                      int ty0, int tx0) {
    const float w0 = 0.0625f, w1 = 0.25f, w2 = 0.375f;
    constexpr int n2    = S - 2 * a;
    constexpr int xg    = n2 / 4;
    constexpr int items = (r1 - r0) * xg;
    for (int idx = threadIdx.x; idx < items; idx += NTHR) {
        int g  = idx % xg;
        int y  = r0 + idx / xg;
        int qr = (y < thr) ? (y - qoffA) : (y - qoffB);
        int x0 = a + 4 * g;                  // logical col of group
        int qp = qr * SP + x0 + SHIFT;       // Q phys, 16B-aligned
        int op = y * SP + x0 + SHIFT;        // P phys
        float c0, c1, c2, c3;
        if constexpr (d == 4) {
            float4 A = *reinterpret_cast<const float4*>(&Q[qp - 8]);
            float4 B = *reinterpret_cast<const float4*>(&Q[qp - 4]);
            float4 C = *reinterpret_cast<const float4*>(&Q[qp]);
            float4 D = *reinterpret_cast<const float4*>(&Q[qp + 4]);
            float4 E = *reinterpret_cast<const float4*>(&Q[qp + 8]);
            float4 AE = f4_add(A, E), BD = f4_add(B, D);
            c0 = w0 * AE.x + w1 * BD.x + w2 * C.x;
            c1 = w0 * AE.y + w1 * BD.y + w2 * C.y;
            c2 = w0 * AE.z + w1 * BD.z + w2 * C.z;
            c3 = w0 * AE.w + w1 * BD.w + w2 * C.w;
        } else {
            constexpr int off = ((a - 2 * d) + SHIFT) & 3;   // 2 (d=1), 0 (d=2)
            constexpr int nw  = (4 * d + 4 + off + 3) & ~3;  // 12 / 12
            int ow = qp - 2 * d - off;                        // 16B-aligned
            float v[nw];
#pragma unroll
            for (int k = 0; k < nw / 4; k++) {
                float4 t4 = *reinterpret_cast<const float4*>(&Q[ow + 4 * k]);
                v[4 * k] = t4.x; v[4 * k + 1] = t4.y;
                v[4 * k + 2] = t4.z; v[4 * k + 3] = t4.w;
            }
            c0 = w2 * v[off + 2 * d]     + w1 * (v[off + d]     + v[off + 3 * d])
               + w0 * (v[off]            + v[off + 4 * d]);
            c1 = w2 * v[off + 2 * d + 1] + w1 * (v[off + d + 1] + v[off + 3 * d + 1])
               + w0 * (v[off + 1]        + v[off + 4 * d + 1]);
            c2 = w2 * v[off + 2 * d + 2] + w1 * (v[off + d + 2] + v[off + 3 * d + 2])
               + w0 * (v[off + 2]        + v[off + 4 * d + 2]);
            c3 = w2 * v[off + 2 * d + 3] + w1 * (v[off + d + 3] + v[off + 3 * d + 3])
               + w0 * (v[off + 3]        + v[off + 4 * d + 3]);
        }
        float4 prev = *reinterpret_cast<const float4*>(&P[op]);
        if constexpr (!LAST)
            *reinterpret_cast<float4*>(&P[op]) = make_float4(c0, c1, c2, c3);
        bool center = (a == HL) ||
                      (y >= HL && y < S - HL && x0 >= HL && x0 < S - HL);
        if (center) {
            int gy = ty0 + y - HL;
            int gx = tx0 + x0 - HL;
            *reinterpret_cast<float4*>(&wch[gy * IMG + gx]) =
                make_float4(prev.x - c0, prev.y - c1, prev.z - c2, prev.w - c3);
            if constexpr (LAST)
                *reinterpret_cast<float4*>(&cch[gy * IMG + gx]) =
                    make_float4(c0, c1, c2, c3);
        }
    }
}

// ---- one level: two bands, 4 phases ----
//      b1/b2: band heights (b1+b2 = S-2a, b2 <= b1-2d, both /8).
template<int d, int h, int a, int b1, bool LAST>
__device__ __forceinline__ void do_level(float* __restrict__ P,
                                         float* __restrict__ Q,
                                         float* __restrict__ wch,
                                         float* __restrict__ cch,
                                         int ty0, int tx0) {
    constexpr int mid = a + b1;
    hpass<d, h, a, a, mid, a>(P, Q);                         // Q slots [0,b1)
    __syncthreads();
    wpass<d, h, a, a, mid - 2 * d, mid, a, a, LAST>(P, Q, wch, cch, ty0, tx0);
    __syncthreads();
    hpass<d, h, a, mid, S - a, mid>(P, Q);                   // Q slots [0,b2)
    __syncthreads();
    wpass<d, h, a, mid - 2 * d, S - a, mid, a, mid, LAST>(P, Q, wch, cch,
                                                          ty0, tx0);
    __syncthreads();
}

__global__ void __launch_bounds__(NTHR, 4) uwt_kernel(const float* __restrict__ x,
                                                      float* __restrict__ out) {
    extern __shared__ float smem[];
    float* P = smem;                 // 92 x 96
    float* Q = smem + S * SP;        // 48 x 96 band

    const int b   = blockIdx.z;
    const int ty0 = blockIdx.y * TS;
    const int tx0 = blockIdx.x * TS;
    const float* xb = x + (size_t)b * IMG * IMG;

    // ---- load c0 with halo ----
    const bool interior = (tx0 >= 64 && tx0 <= IMG - TS - 16) &&
                          (ty0 >= 64 && ty0 <= IMG - TS - 16);
    if (interior) {
        const float* src = xb + (size_t)(ty0 - HL) * IMG + (tx0 - 16);
        for (int idx = threadIdx.x; idx < S * (SP / 4); idx += NTHR) {
            int ly = idx / (SP / 4);
            int k  = idx - ly * (SP / 4);
            float4 v4 = *reinterpret_cast<const float4*>(src + (size_t)ly * IMG + 4 * k);
            *reinterpret_cast<float4*>(&P[ly * SP + 4 * k]) = v4;
        }
    } else {
        for (int idx = threadIdx.x; idx < S * S; idx += NTHR) {
            int ly = idx / S;
            int lx = idx - ly * S;
            int gy = reflect_idx(ty0 + ly - HL);
            int gx = reflect_idx(tx0 + lx - HL);
            P[ly * SP + lx + SHIFT] = xb[gy * IMG + gx];
        }
    }
    __syncthreads();

    float* ob = out + (size_t)b * 4 * IMG * IMG;
    // L1: R=88 -> b1=48,b2=40 (40<=46); L2: R=80 -> 48/32 (32<=44);
    // L3: R=64 -> 40/24 (24<=32). Q capacity 48.
    do_level<1, 0, 2, 48, false>(P, Q, ob + 0 * IMG * IMG, nullptr, ty0, tx0);
    do_level<2, 2, 6, 48, false>(P, Q, ob + 1 * IMG * IMG, nullptr, ty0, tx0);
    do_level<4, 6, 14, 40, true>(P, Q, ob + 2 * IMG * IMG, ob + 3 * IMG * IMG,
                                 ty0, tx0);
}

extern "C" void kernel_launch(void* const* d_in, const int* in_sizes, int n_in,
                              void* d_out, int out_size) {
    const float* x = (const float*)d_in[0];
    float* out     = (float*)d_out;

    cudaFuncSetAttribute(uwt_kernel, cudaFuncAttributeMaxDynamicSharedMemorySize,
                         (int)SMEM_BYTES);

    dim3 grid(IMG / TS, IMG / TS, 8);
    uwt_kernel<<<grid, NTHR, SMEM_BYTES>>>(x, out);
}